// round 13
// baseline (speedup 1.0000x reference)
#include <cuda_runtime.h>
#include <cuda_bf16.h>
#include <cstdint>

#define BB 2048
#define SS 200
#define TS 64
#define EPSV 1e-9f
#define ASTRIDE 72    // bf16 row stride: 144B, granule stride 9 -> conflict-free ldmatrix
#define HSTRIDE 72
#define GRID 456      // 3 CTAs/SM x 152 SMs, persistent

__device__ int g_ctr  = GRID;   // work-pop counter; self-resets each launch
__device__ int g_done = 0;      // completed-batch counter; self-resets

struct alignas(16) Smem {
    __nv_bfloat16 Ahi[2][64][ASTRIDE];     // double-buffered A = k tile, bf16 hi
    __nv_bfloat16 Alo[2][64][ASTRIDE];     // bf16 lo (residual)
    union {
        struct {
            __nv_bfloat16 H1hi[64][HSTRIDE];
            __nv_bfloat16 H1lo[64][HSTRIDE];
        } hh;                              // per-tile hidden
        float  Qpart[256];                 // batch-start qbias partials
        float2 Red2[256];                  // batch-end output reduce
    } h;
    uint32_t B2[4][32][33];                // stage-2 W2 fragments (odd stride)
    float Score[64];
    float Q[64];
    float a1[64], m1[64], r1[64];
    float4 P2[16];                         // {mean2, rsqrt(var2+eps), alpha2, W3}
    int Lslot, bnext;
};

__device__ __forceinline__ float fast_sigmoid(float x) {
    return __fdividef(1.0f, 1.0f + __expf(-x));
}
__device__ __forceinline__ uint32_t sptr(const void* p) {
    return (uint32_t)__cvta_generic_to_shared(p);
}
__device__ __forceinline__ void ldsm4(uint32_t r[4], uint32_t addr) {
    asm volatile("ldmatrix.sync.aligned.m8n8.x4.shared.b16 {%0,%1,%2,%3}, [%4];"
                 : "=r"(r[0]), "=r"(r[1]), "=r"(r[2]), "=r"(r[3]) : "r"(addr));
}
__device__ __forceinline__ void mma16816(float c[4], const uint32_t a[4], const uint32_t b[2]) {
    asm volatile("mma.sync.aligned.m16n8k16.row.col.f32.bf16.bf16.f32 "
                 "{%0,%1,%2,%3},{%4,%5,%6,%7},{%8,%9},{%0,%1,%2,%3};"
                 : "+f"(c[0]), "+f"(c[1]), "+f"(c[2]), "+f"(c[3])
                 : "r"(a[0]), "r"(a[1]), "r"(a[2]), "r"(a[3]), "r"(b[0]), "r"(b[1]));
}
__device__ __forceinline__ void hl_split(float x, unsigned short& h, unsigned short& l) {
    __nv_bfloat16 hb = __float2bfloat16_rn(x);
    float r = x - __bfloat162float(hb);
    __nv_bfloat16 lb = __float2bfloat16_rn(r);
    h = __bfloat16_as_ushort(hb);
    l = __bfloat16_as_ushort(lb);
}
__device__ __forceinline__ uint32_t pk(unsigned short lo, unsigned short hi) {
    return ((uint32_t)hi << 16) | lo;
}
__device__ __forceinline__ void split2(float x, float y, uint32_t& ph, uint32_t& pl) {
    unsigned short xh, xl, yh, yl;
    hl_split(x, xh, xl);
    hl_split(y, yh, yl);
    ph = pk(xh, yh);
    pl = pk(xl, yl);
}
__device__ __forceinline__ float dice_apply(float x, float m, float r, float a) {
    float p = fast_sigmoid((x - m) * r);
    return x * (a + p * (1.0f - a));
}

__global__ void __launch_bounds__(256, 3) din_pool_kernel(
    const float* __restrict__ q_emb,
    const float* __restrict__ k_emb,
    const int*   __restrict__ seqlen,
    const float* __restrict__ W1,
    const float* __restrict__ alpha1,
    const float* __restrict__ mean1,
    const float* __restrict__ var1,
    const float* __restrict__ W2,
    const float* __restrict__ alpha2,
    const float* __restrict__ mean2,
    const float* __restrict__ var2,
    const float* __restrict__ W3,
    float* __restrict__ out)
{
    extern __shared__ char smem_raw[];
    Smem& sm = *reinterpret_cast<Smem*>(smem_raw);

    const int tid  = threadIdx.x;
    const int lane = tid & 31;
    const int wid  = tid >> 5;

    // builder geometry: thread owns cols c4e..c4e+3 of rows srow0 + 16*it
    const int c4e   = (tid & 15) * 4;
    const int srow0 = tid >> 4;

    auto pf_load = [&](int bb, int s0, float4 pf[4]) {
        const float* base = k_emb + (long)bb * SS * 64 + c4e;
        #pragma unroll
        for (int it = 0; it < 4; it++) {
            int gs = s0 + srow0 + it * 16;
            float4 v = make_float4(0.f, 0.f, 0.f, 0.f);
            if (gs < SS) v = *reinterpret_cast<const float4*>(base + (long)gs * 64);
            pf[it] = v;
        }
    };
    auto build_A = [&](int p, const float4 pf[4]) {
        #pragma unroll
        for (int it = 0; it < 4; it++) {
            int s = srow0 + it * 16;
            float4 kv = pf[it];
            uint32_t h0, l0, h1, l1;
            split2(kv.x, kv.y, h0, l0);
            split2(kv.z, kv.w, h1, l1);
            *reinterpret_cast<uint2*>(&sm.Ahi[p][s][c4e]) = make_uint2(h0, h1);
            *reinterpret_cast<uint2*>(&sm.Alo[p][s][c4e]) = make_uint2(l0, l1);
        }
    };

    // ---- issue tile-0 loads immediately; prologue hides the latency ----
    int b_cur = blockIdx.x;            // GRID < BB, always valid
    float4 pf[4];
    pf_load(b_cur, 0, pf);

    // ================= one-time prologue (no weight staging) =================
    if (tid < 16)
        sm.P2[tid] = make_float4(mean2[tid], rsqrtf(var2[tid] + EPSV),
                                 alpha2[tid], W3[tid]);
    if (tid < 64) {
        sm.a1[tid] = alpha1[tid];
        sm.m1[tid] = mean1[tid];
        sm.r1[tid] = rsqrtf(var1[tid] + EPSV);
    }
    // B2 fragments straight from gmem W2 (warps 0..3)
    if (wid < 4) {
        int n = lane >> 2;
        #pragma unroll
        for (int kt = 0; kt < 4; kt++) {
            int kb = kt * 16 + 2 * (lane & 3);
            #pragma unroll
            for (int nt = 0; nt < 2; nt++) {
                int col = n + 8 * nt;
                float w0 = W2[kb * 16 + col];
                float w1 = W2[(kb + 1) * 16 + col];
                float w8 = W2[(kb + 8) * 16 + col];
                float w9 = W2[(kb + 9) * 16 + col];
                uint32_t h0, l0, h1, l1;
                split2(w0, w1, h0, l0);
                split2(w8, w9, h1, l1);
                sm.B2[wid][lane][kt * 8 + nt * 4 + 0] = h0;
                sm.B2[wid][lane][kt * 8 + nt * 4 + 1] = h1;
                sm.B2[wid][lane][kt * 8 + nt * 4 + 2] = l0;
                sm.B2[wid][lane][kt * 8 + nt * 4 + 3] = l1;
            }
        }
    }
    // build first tile into buffer 0 (batch-start syncs make it visible)
    build_A(0, pf);
    int p = 0;
    __syncthreads();

    // Hoisted constants
    const int n0   = 8 * wid + 2 * (lane & 3);    // stage-1 cols
    const float d1m0 = sm.m1[n0],     d1r0 = sm.r1[n0],     d1a0 = sm.a1[n0];
    const float d1m1 = sm.m1[n0 + 1], d1r1 = sm.r1[n0 + 1], d1a1 = sm.a1[n0 + 1];
    const int arow = lane & 15;
    const int acol = (lane & 16) ? 8 : 0;
    const int eL   = tid & 31;
    const int er   = tid >> 5;

    // ================= persistent batch loop =================
    while (b_cur < BB) {
        if (tid == 0) {
            sm.bnext = atomicAdd(&g_ctr, 1);
            sm.Lslot = seqlen[b_cur];
        }
        if (tid < 64) sm.Q[tid] = q_emb[b_cur * 64 + tid];
        __syncthreads();
        const int L      = sm.Lslot;
        const int b_next = sm.bnext;
        const int T      = (L + TS - 1) >> 6;

        // ---- Qbias partials: q @ (W1a + W1c), coalesced gmem (L2-hot) ----
        {
            int hcol = tid & 63, g = tid >> 6;
            const float* W1a = W1 + (g * 16) * 64 + hcol;
            const float* W1c = W1 + (128 + g * 16) * 64 + hcol;
            float acc = 0.f;
            #pragma unroll
            for (int d = 0; d < 16; d++)
                acc = fmaf(sm.Q[g * 16 + d], W1a[d * 64] + W1c[d * 64], acc);
            sm.h.Qpart[tid] = acc;
        }

        // ---- B1 fragments per batch: W_eff = (W1b - W1c) + q * W1d ----
        uint32_t b1hi[4][2], b1lo[4][2];
        {
            int n = 8 * wid + (lane >> 2);
            #pragma unroll
            for (int kt = 0; kt < 4; kt++) {
                int kb = kt * 16 + 2 * (lane & 3);
                float w[4];
                #pragma unroll
                for (int j = 0; j < 4; j++) {
                    int d = kb + ((j & 1) ? 1 : 0) + ((j & 2) ? 8 : 0);  // {0,1,8,9}
                    float wb = W1[(64 + d) * 64 + n];
                    float wc = W1[(128 + d) * 64 + n];
                    float wd = W1[(192 + d) * 64 + n];
                    w[j] = (wb - wc) + sm.Q[d] * wd;
                }
                split2(w[0], w[1], b1hi[kt][0], b1lo[kt][0]);
                split2(w[2], w[3], b1hi[kt][1], b1lo[kt][1]);
            }
        }
        __syncthreads();
        const float bia0 = sm.h.Qpart[n0]       + sm.h.Qpart[64 + n0]
                         + sm.h.Qpart[128 + n0] + sm.h.Qpart[192 + n0];
        const float bia1 = sm.h.Qpart[n0 + 1]       + sm.h.Qpart[64 + n0 + 1]
                         + sm.h.Qpart[128 + n0 + 1] + sm.h.Qpart[192 + n0 + 1];
        __syncthreads();   // Qpart reads done; h-region free for H1

        float2 po = make_float2(0.f, 0.f);

        for (int t = 0; t < T; t++) {
            const int s0 = t << 6;

            // ---- successor-tile target (same for pf_load and build) ----
            int nb = -1, ns = 0;
            if (t + 1 < T)          { nb = b_cur;  ns = s0 + TS; }
            else if (b_next < BB)   { nb = b_next; ns = 0; }
            if (nb >= 0) pf_load(nb, ns, pf);   // consumed at bottom; full-tile latency

            // ---- stage 1: H1 = A[p](64x64) @ W_eff(64x64), 4 k-steps ----
            float c1[4][4];
            #pragma unroll
            for (int mi = 0; mi < 4; mi++) {
                c1[mi][0] = bia0; c1[mi][1] = bia1;
                c1[mi][2] = bia0; c1[mi][3] = bia1;
            }
            #pragma unroll
            for (int kt = 0; kt < 4; kt++) {
                #pragma unroll
                for (int mi = 0; mi < 4; mi++) {
                    uint32_t ah[4], al[4];
                    ldsm4(ah, sptr(&sm.Ahi[p][mi * 16 + arow][kt * 16 + acol]));
                    ldsm4(al, sptr(&sm.Alo[p][mi * 16 + arow][kt * 16 + acol]));
                    mma16816(c1[mi], ah, b1hi[kt]);
                    mma16816(c1[mi], al, b1hi[kt]);
                    mma16816(c1[mi], ah, b1lo[kt]);
                }
            }
            // Dice1 + store H1 hi/lo
            #pragma unroll
            for (int mi = 0; mi < 4; mi++) {
                int r0 = mi * 16 + (lane >> 2);
                uint32_t ph, pl;
                float x0 = dice_apply(c1[mi][0], d1m0, d1r0, d1a0);
                float x1 = dice_apply(c1[mi][1], d1m1, d1r1, d1a1);
                split2(x0, x1, ph, pl);
                *reinterpret_cast<uint32_t*>(&sm.h.hh.H1hi[r0][n0]) = ph;
                *reinterpret_cast<uint32_t*>(&sm.h.hh.H1lo[r0][n0]) = pl;
                float x2 = dice_apply(c1[mi][2], d1m0, d1r0, d1a0);
                float x3 = dice_apply(c1[mi][3], d1m1, d1r1, d1a1);
                split2(x2, x3, ph, pl);
                *reinterpret_cast<uint32_t*>(&sm.h.hh.H1hi[r0 + 8][n0]) = ph;
                *reinterpret_cast<uint32_t*>(&sm.h.hh.H1lo[r0 + 8][n0]) = pl;
            }
            __syncthreads();

            // ---- stage 2 (warps 0..3): mma with smem B2 + fused score ----
            if (wid < 4) {
                const uint32_t* bp = &sm.B2[wid][lane][0];
                float c2[2][4];
                c2[0][0]=c2[0][1]=c2[0][2]=c2[0][3]=0.f;
                c2[1][0]=c2[1][1]=c2[1][2]=c2[1][3]=0.f;
                #pragma unroll
                for (int kt = 0; kt < 4; kt++) {
                    uint32_t ah[4], al[4];
                    ldsm4(ah, sptr(&sm.h.hh.H1hi[wid * 16 + arow][kt * 16 + acol]));
                    ldsm4(al, sptr(&sm.h.hh.H1lo[wid * 16 + arow][kt * 16 + acol]));
                    #pragma unroll
                    for (int nt = 0; nt < 2; nt++) {
                        uint32_t bh[2] = { bp[kt * 8 + nt * 4 + 0], bp[kt * 8 + nt * 4 + 1] };
                        uint32_t bl[2] = { bp[kt * 8 + nt * 4 + 2], bp[kt * 8 + nt * 4 + 3] };
                        mma16816(c2[nt], ah, bh);
                        mma16816(c2[nt], al, bh);
                        mma16816(c2[nt], ah, bl);
                    }
                }
                float pr0 = 0.f, pr1 = 0.f;
                #pragma unroll
                for (int nt = 0; nt < 2; nt++) {
                    int cc = 8 * nt + 2 * (lane & 3);
                    float4 pA = sm.P2[cc];
                    float4 pB = sm.P2[cc + 1];
                    pr0 += dice_apply(c2[nt][0], pA.x, pA.y, pA.z) * pA.w
                         + dice_apply(c2[nt][1], pB.x, pB.y, pB.z) * pB.w;
                    pr1 += dice_apply(c2[nt][2], pA.x, pA.y, pA.z) * pA.w
                         + dice_apply(c2[nt][3], pB.x, pB.y, pB.z) * pB.w;
                }
                pr0 += __shfl_xor_sync(0xffffffffu, pr0, 1);
                pr0 += __shfl_xor_sync(0xffffffffu, pr0, 2);
                pr1 += __shfl_xor_sync(0xffffffffu, pr1, 1);
                pr1 += __shfl_xor_sync(0xffffffffu, pr1, 2);
                if ((lane & 3) == 0) {
                    int r0 = wid * 16 + (lane >> 2);
                    int gs0 = s0 + r0;
                    sm.Score[r0]     = (gs0 < L)     ? fast_sigmoid(pr0) : 0.0f;
                    sm.Score[r0 + 8] = (gs0 + 8 < L) ? fast_sigmoid(pr1) : 0.0f;
                }
            }
            __syncthreads();

            // ---- epilogue: po += score[s] * k[s][cols], k = Ahi + Alo ----
            #pragma unroll
            for (int i = 0; i < 8; i++) {
                int s = (er << 3) + i;
                float sc = sm.Score[s];
                __nv_bfloat162 hh = *reinterpret_cast<const __nv_bfloat162*>(&sm.Ahi[p][s][2 * eL]);
                __nv_bfloat162 ll = *reinterpret_cast<const __nv_bfloat162*>(&sm.Alo[p][s][2 * eL]);
                float2 hf = __bfloat1622float2(hh);
                float2 lf = __bfloat1622float2(ll);
                po.x = fmaf(sc, hf.x + lf.x, po.x);
                po.y = fmaf(sc, hf.y + lf.y, po.y);
            }

            // ---- build successor tile into the OTHER buffer (no sync needed:
            //      epilogue reads A[p], build writes A[1-p]; A[1-p]'s previous
            //      readers finished before this tile's H1 sync) ----
            if (nb >= 0) build_A(p ^ 1, pf);
            p ^= 1;
            __syncthreads();   // loop-top equivalent: build visible / A consumed
        }

        // ---- output (Red2 aliases dead H1 region) ----
        sm.h.Red2[tid] = po;
        __syncthreads();
        if (tid < 32) {
            float2 acc = sm.h.Red2[tid];
            #pragma unroll
            for (int g = 1; g < 8; g++) {
                float2 v = sm.h.Red2[g * 32 + tid];
                acc.x += v.x; acc.y += v.y;
            }
            out[b_cur * 64 + 2 * tid]     = acc.x;
            out[b_cur * 64 + 2 * tid + 1] = acc.y;
        }
        // counter self-reset: CTA finishing the globally-last batch restores g_ctr
        if (tid == 0) {
            int od = atomicAdd(&g_done, 1);
            if (od == BB - 1) {
                g_done = 0;
                __threadfence();
                g_ctr = GRID;
            }
        }
        b_cur = b_next;
    }
}

extern "C" void kernel_launch(void* const* d_in, const int* in_sizes, int n_in,
                              void* d_out, int out_size) {
    const float* q      = (const float*)d_in[0];
    const float* k      = (const float*)d_in[1];
    const int*   sl     = (const int*)  d_in[2];
    const float* W1     = (const float*)d_in[3];
    const float* alpha1 = (const float*)d_in[4];
    const float* mean1  = (const float*)d_in[5];
    const float* var1   = (const float*)d_in[6];
    const float* W2     = (const float*)d_in[7];
    const float* alpha2 = (const float*)d_in[8];
    const float* mean2  = (const float*)d_in[9];
    const float* var2   = (const float*)d_in[10];
    const float* W3     = (const float*)d_in[11];
    float* out = (float*)d_out;

    cudaFuncSetAttribute(din_pool_kernel,
                         cudaFuncAttributeMaxDynamicSharedMemorySize,
                         (int)sizeof(Smem));
    din_pool_kernel<<<GRID, 256, sizeof(Smem)>>>(
        q, k, sl, W1, alpha1, mean1, var1, W2, alpha2, mean2, var2, W3, out);
}

// round 15
// speedup vs baseline: 1.2712x; 1.2712x over previous
#include <cuda_runtime.h>
#include <cuda_bf16.h>
#include <cstdint>

#define BB 2048
#define SS 200
#define TS 64
#define EPSV 1e-9f
#define ASTRIDE 72    // bf16 row stride: 144B, granule stride 9 -> conflict-free ldmatrix
#define HSTRIDE 72
#define GRID 456      // 3 CTAs/SM x 152 SMs, persistent

__device__ int g_ctr  = GRID;   // work-pop counter; self-resets each launch
__device__ int g_done = 0;      // completed-batch counter; self-resets

struct alignas(16) Smem {
    __nv_bfloat16 Ahi[64][ASTRIDE];        // A = k tile, bf16 hi
    __nv_bfloat16 Alo[64][ASTRIDE];        // bf16 lo (residual)
    float Kraw[64][68];                    // cp.async staging of next K tile
    union {
        struct {
            __nv_bfloat16 H1hi[64][HSTRIDE];
            __nv_bfloat16 H1lo[64][HSTRIDE];
        } hh;                              // per-tile hidden
        float  Qpart[256];                 // batch-start qbias partials
        float2 Red2[256];                  // batch-end output reduce
    } h;
    uint32_t B2[4][32][33];                // stage-2 W2 fragments (odd stride)
    float Score[64];
    float Q[64];
    float a1[64], m1[64], r1[64];
    float4 P2[16];                         // {mean2, rsqrt(var2+eps), alpha2, W3}
    int Lslot, bnext;
};

__device__ __forceinline__ float fast_sigmoid(float x) {
    return __fdividef(1.0f, 1.0f + __expf(-x));
}
__device__ __forceinline__ uint32_t sptr(const void* p) {
    return (uint32_t)__cvta_generic_to_shared(p);
}
__device__ __forceinline__ void ldsm4(uint32_t r[4], uint32_t addr) {
    asm volatile("ldmatrix.sync.aligned.m8n8.x4.shared.b16 {%0,%1,%2,%3}, [%4];"
                 : "=r"(r[0]), "=r"(r[1]), "=r"(r[2]), "=r"(r[3]) : "r"(addr));
}
__device__ __forceinline__ void mma16816(float c[4], const uint32_t a[4], const uint32_t b[2]) {
    asm volatile("mma.sync.aligned.m16n8k16.row.col.f32.bf16.bf16.f32 "
                 "{%0,%1,%2,%3},{%4,%5,%6,%7},{%8,%9},{%0,%1,%2,%3};"
                 : "+f"(c[0]), "+f"(c[1]), "+f"(c[2]), "+f"(c[3])
                 : "r"(a[0]), "r"(a[1]), "r"(a[2]), "r"(a[3]), "r"(b[0]), "r"(b[1]));
}
__device__ __forceinline__ void hl_split(float x, unsigned short& h, unsigned short& l) {
    __nv_bfloat16 hb = __float2bfloat16_rn(x);
    float r = x - __bfloat162float(hb);
    __nv_bfloat16 lb = __float2bfloat16_rn(r);
    h = __bfloat16_as_ushort(hb);
    l = __bfloat16_as_ushort(lb);
}
__device__ __forceinline__ uint32_t pk(unsigned short lo, unsigned short hi) {
    return ((uint32_t)hi << 16) | lo;
}
__device__ __forceinline__ void split2(float x, float y, uint32_t& ph, uint32_t& pl) {
    unsigned short xh, xl, yh, yl;
    hl_split(x, xh, xl);
    hl_split(y, yh, yl);
    ph = pk(xh, yh);
    pl = pk(xl, yl);
}
__device__ __forceinline__ float dice_apply(float x, float m, float r, float a) {
    float p = fast_sigmoid((x - m) * r);
    return x * (a + p * (1.0f - a));
}

__global__ void __launch_bounds__(256, 3) din_pool_kernel(
    const float* __restrict__ q_emb,
    const float* __restrict__ k_emb,
    const int*   __restrict__ seqlen,
    const float* __restrict__ W1,
    const float* __restrict__ alpha1,
    const float* __restrict__ mean1,
    const float* __restrict__ var1,
    const float* __restrict__ W2,
    const float* __restrict__ alpha2,
    const float* __restrict__ mean2,
    const float* __restrict__ var2,
    const float* __restrict__ W3,
    float* __restrict__ out)
{
    extern __shared__ char smem_raw[];
    Smem& sm = *reinterpret_cast<Smem*>(smem_raw);

    const int tid  = threadIdx.x;
    const int lane = tid & 31;
    const int wid  = tid >> 5;

    auto prefetch_tile = [&](int bb, int s0) {
        const long base = (long)bb * SS * 64;
        #pragma unroll
        for (int it = 0; it < 4; it++) {
            int i = tid + it * 256;
            int s = i >> 4, c4 = (i & 15) * 4;
            int gs = s0 + s;
            int gsc = (gs < SS) ? gs : 0;
            uint32_t dst = sptr(&sm.Kraw[s][c4]);
            const float* src = &k_emb[base + (long)gsc * 64 + c4];
            int szn = (gs < SS) ? 16 : 0;
            asm volatile("cp.async.ca.shared.global [%0], [%1], 16, %2;"
                         :: "r"(dst), "l"(src), "r"(szn));
        }
        asm volatile("cp.async.commit_group;");
    };

    // ---- issue tile-0 prefetch immediately; prologue hides it ----
    int b_cur = blockIdx.x;            // GRID < BB, always valid
    prefetch_tile(b_cur, 0);

    // ================= one-time prologue (no weight staging) =================
    if (tid < 16)
        sm.P2[tid] = make_float4(mean2[tid], rsqrtf(var2[tid] + EPSV),
                                 alpha2[tid], W3[tid]);
    if (tid < 64) {
        sm.a1[tid] = alpha1[tid];
        sm.m1[tid] = mean1[tid];
        sm.r1[tid] = rsqrtf(var1[tid] + EPSV);
    }
    // B2 fragments straight from gmem W2 (warps 0..3)
    if (wid < 4) {
        int n = lane >> 2;
        #pragma unroll
        for (int kt = 0; kt < 4; kt++) {
            int kb = kt * 16 + 2 * (lane & 3);
            #pragma unroll
            for (int nt = 0; nt < 2; nt++) {
                int col = n + 8 * nt;
                float w0 = W2[kb * 16 + col];
                float w1 = W2[(kb + 1) * 16 + col];
                float w8 = W2[(kb + 8) * 16 + col];
                float w9 = W2[(kb + 9) * 16 + col];
                uint32_t h0, l0, h1, l1;
                split2(w0, w1, h0, l0);
                split2(w8, w9, h1, l1);
                sm.B2[wid][lane][kt * 8 + nt * 4 + 0] = h0;
                sm.B2[wid][lane][kt * 8 + nt * 4 + 1] = h1;
                sm.B2[wid][lane][kt * 8 + nt * 4 + 2] = l0;
                sm.B2[wid][lane][kt * 8 + nt * 4 + 3] = l1;
            }
        }
    }
    __syncthreads();

    // Hoisted constants
    // stage-1 warp tile: 32 rows x 16 cols
    const int rbase = (wid >> 2) * 32;            // M half
    const int cbase = (wid & 3) * 16;             // N quarter
    const int n0a   = cbase + 2 * (lane & 3);     // nt=0 col pair
    const int n0b   = n0a + 8;                    // nt=1 col pair
    const int arow = lane & 15;
    const int acol = (lane & 16) ? 8 : 0;
    const int c4e   = (tid & 15) * 4;             // builder cols
    const int srow0 = tid >> 4;                   // builder base row
    const int eL   = tid & 31;
    const int er   = tid >> 5;

    // ================= persistent batch loop =================
    while (b_cur < BB) {
        if (tid == 0) {
            sm.bnext = atomicAdd(&g_ctr, 1);
            sm.Lslot = seqlen[b_cur];
        }
        if (tid < 64) sm.Q[tid] = q_emb[b_cur * 64 + tid];
        __syncthreads();
        const int L      = sm.Lslot;
        const int b_next = sm.bnext;
        const int T      = (L + TS - 1) >> 6;

        // ---- Qbias partials: q @ (W1a + W1c), coalesced gmem (L2-hot) ----
        {
            int hcol = tid & 63, g = tid >> 6;
            const float* W1a = W1 + (g * 16) * 64 + hcol;
            const float* W1c = W1 + (128 + g * 16) * 64 + hcol;
            float acc = 0.f;
            #pragma unroll
            for (int d = 0; d < 16; d++)
                acc = fmaf(sm.Q[g * 16 + d], W1a[d * 64] + W1c[d * 64], acc);
            sm.h.Qpart[tid] = acc;
        }

        // ---- B1 fragments per batch: W_eff = (W1b - W1c) + q * W1d ----
        // 2 n-strips per warp (cols cbase..cbase+15)
        uint32_t b1hi[4][2][2], b1lo[4][2][2];
        {
            #pragma unroll
            for (int kt = 0; kt < 4; kt++) {
                int kb = kt * 16 + 2 * (lane & 3);
                #pragma unroll
                for (int nt = 0; nt < 2; nt++) {
                    int n = cbase + 8 * nt + (lane >> 2);
                    float w[4];
                    #pragma unroll
                    for (int j = 0; j < 4; j++) {
                        int d = kb + ((j & 1) ? 1 : 0) + ((j & 2) ? 8 : 0);  // {0,1,8,9}
                        float wb = W1[(64 + d) * 64 + n];
                        float wc = W1[(128 + d) * 64 + n];
                        float wd = W1[(192 + d) * 64 + n];
                        w[j] = (wb - wc) + sm.Q[d] * wd;
                    }
                    split2(w[0], w[1], b1hi[kt][nt][0], b1lo[kt][nt][0]);
                    split2(w[2], w[3], b1hi[kt][nt][1], b1lo[kt][nt][1]);
                }
            }
        }
        __syncthreads();
        const float biaA0 = sm.h.Qpart[n0a]       + sm.h.Qpart[64 + n0a]
                          + sm.h.Qpart[128 + n0a] + sm.h.Qpart[192 + n0a];
        const float biaA1 = sm.h.Qpart[n0a + 1]       + sm.h.Qpart[64 + n0a + 1]
                          + sm.h.Qpart[128 + n0a + 1] + sm.h.Qpart[192 + n0a + 1];
        const float biaB0 = sm.h.Qpart[n0b]       + sm.h.Qpart[64 + n0b]
                          + sm.h.Qpart[128 + n0b] + sm.h.Qpart[192 + n0b];
        const float biaB1 = sm.h.Qpart[n0b + 1]       + sm.h.Qpart[64 + n0b + 1]
                          + sm.h.Qpart[128 + n0b + 1] + sm.h.Qpart[192 + n0b + 1];
        __syncthreads();   // Qpart reads done; h-region free for H1

        float2 po = make_float2(0.f, 0.f);

        for (int t = 0; t < T; t++) {
            const int s0 = t << 6;
            asm volatile("cp.async.wait_group 0;" ::: "memory");
            __syncthreads();   // Kraw ready; A free from prev epilogue

            // ---- build A (k only, bf16 hi/lo) from Kraw ----
            #pragma unroll
            for (int it = 0; it < 4; it++) {
                int s = srow0 + it * 16;
                float4 kv = *reinterpret_cast<const float4*>(&sm.Kraw[s][c4e]);
                uint32_t h0, l0, h1, l1;
                split2(kv.x, kv.y, h0, l0);
                split2(kv.z, kv.w, h1, l1);
                *reinterpret_cast<uint2*>(&sm.Ahi[s][c4e]) = make_uint2(h0, h1);
                *reinterpret_cast<uint2*>(&sm.Alo[s][c4e]) = make_uint2(l0, l1);
            }
            __syncthreads();   // A visible; Kraw free

            // ---- prefetch successor tile ----
            if (t + 1 < T)          prefetch_tile(b_cur, s0 + TS);
            else if (b_next < BB)   prefetch_tile(b_next, 0);

            // ---- stage 1: warp computes 32x16 block of H1, 4 k-steps ----
            float c1[2][2][4];
            #pragma unroll
            for (int mi = 0; mi < 2; mi++) {
                c1[mi][0][0] = biaA0; c1[mi][0][1] = biaA1;
                c1[mi][0][2] = biaA0; c1[mi][0][3] = biaA1;
                c1[mi][1][0] = biaB0; c1[mi][1][1] = biaB1;
                c1[mi][1][2] = biaB0; c1[mi][1][3] = biaB1;
            }
            #pragma unroll
            for (int kt = 0; kt < 4; kt++) {
                #pragma unroll
                for (int mi = 0; mi < 2; mi++) {
                    uint32_t ah[4], al[4];
                    ldsm4(ah, sptr(&sm.Ahi[rbase + mi * 16 + arow][kt * 16 + acol]));
                    ldsm4(al, sptr(&sm.Alo[rbase + mi * 16 + arow][kt * 16 + acol]));
                    #pragma unroll
                    for (int nt = 0; nt < 2; nt++) {
                        mma16816(c1[mi][nt], ah, b1hi[kt][nt]);
                        mma16816(c1[mi][nt], al, b1hi[kt][nt]);
                        mma16816(c1[mi][nt], ah, b1lo[kt][nt]);
                    }
                }
            }
            // Dice1 (params from smem) + store H1 hi/lo
            #pragma unroll
            for (int mi = 0; mi < 2; mi++) {
                #pragma unroll
                for (int nt = 0; nt < 2; nt++) {
                    int nn = nt ? n0b : n0a;
                    float m0 = sm.m1[nn],     rv0 = sm.r1[nn],     a0 = sm.a1[nn];
                    float m1v = sm.m1[nn + 1], rv1 = sm.r1[nn + 1], a1v = sm.a1[nn + 1];
                    int r0 = rbase + mi * 16 + (lane >> 2);
                    uint32_t ph, pl;
                    float x0 = dice_apply(c1[mi][nt][0], m0, rv0, a0);
                    float x1 = dice_apply(c1[mi][nt][1], m1v, rv1, a1v);
                    split2(x0, x1, ph, pl);
                    *reinterpret_cast<uint32_t*>(&sm.h.hh.H1hi[r0][nn]) = ph;
                    *reinterpret_cast<uint32_t*>(&sm.h.hh.H1lo[r0][nn]) = pl;
                    float x2 = dice_apply(c1[mi][nt][2], m0, rv0, a0);
                    float x3 = dice_apply(c1[mi][nt][3], m1v, rv1, a1v);
                    split2(x2, x3, ph, pl);
                    *reinterpret_cast<uint32_t*>(&sm.h.hh.H1hi[r0 + 8][nn]) = ph;
                    *reinterpret_cast<uint32_t*>(&sm.h.hh.H1lo[r0 + 8][nn]) = pl;
                }
            }
            __syncthreads();

            // ---- stage 2 (warps 0..3): mma with smem B2 + fused score ----
            if (wid < 4) {
                const uint32_t* bp = &sm.B2[wid][lane][0];
                float c2[2][4];
                c2[0][0]=c2[0][1]=c2[0][2]=c2[0][3]=0.f;
                c2[1][0]=c2[1][1]=c2[1][2]=c2[1][3]=0.f;
                #pragma unroll
                for (int kt = 0; kt < 4; kt++) {
                    uint32_t ah[4], al[4];
                    ldsm4(ah, sptr(&sm.h.hh.H1hi[wid * 16 + arow][kt * 16 + acol]));
                    ldsm4(al, sptr(&sm.h.hh.H1lo[wid * 16 + arow][kt * 16 + acol]));
                    #pragma unroll
                    for (int nt = 0; nt < 2; nt++) {
                        uint32_t bh[2] = { bp[kt * 8 + nt * 4 + 0], bp[kt * 8 + nt * 4 + 1] };
                        uint32_t bl[2] = { bp[kt * 8 + nt * 4 + 2], bp[kt * 8 + nt * 4 + 3] };
                        mma16816(c2[nt], ah, bh);
                        mma16816(c2[nt], al, bh);
                        mma16816(c2[nt], ah, bl);
                    }
                }
                float pr0 = 0.f, pr1 = 0.f;
                #pragma unroll
                for (int nt = 0; nt < 2; nt++) {
                    int cc = 8 * nt + 2 * (lane & 3);
                    float4 pA = sm.P2[cc];
                    float4 pB = sm.P2[cc + 1];
                    pr0 += dice_apply(c2[nt][0], pA.x, pA.y, pA.z) * pA.w
                         + dice_apply(c2[nt][1], pB.x, pB.y, pB.z) * pB.w;
                    pr1 += dice_apply(c2[nt][2], pA.x, pA.y, pA.z) * pA.w
                         + dice_apply(c2[nt][3], pB.x, pB.y, pB.z) * pB.w;
                }
                pr0 += __shfl_xor_sync(0xffffffffu, pr0, 1);
                pr0 += __shfl_xor_sync(0xffffffffu, pr0, 2);
                pr1 += __shfl_xor_sync(0xffffffffu, pr1, 1);
                pr1 += __shfl_xor_sync(0xffffffffu, pr1, 2);
                if ((lane & 3) == 0) {
                    int r0 = wid * 16 + (lane >> 2);
                    int gs0 = s0 + r0;
                    sm.Score[r0]     = (gs0 < L)     ? fast_sigmoid(pr0) : 0.0f;
                    sm.Score[r0 + 8] = (gs0 + 8 < L) ? fast_sigmoid(pr1) : 0.0f;
                }
            }
            __syncthreads();

            // ---- epilogue: po += score[s] * k[s][cols], k = Ahi + Alo ----
            #pragma unroll
            for (int i = 0; i < 8; i++) {
                int s = (er << 3) + i;
                float sc = sm.Score[s];
                __nv_bfloat162 hh = *reinterpret_cast<const __nv_bfloat162*>(&sm.Ahi[s][2 * eL]);
                __nv_bfloat162 ll = *reinterpret_cast<const __nv_bfloat162*>(&sm.Alo[s][2 * eL]);
                float2 hf = __bfloat1622float2(hh);
                float2 lf = __bfloat1622float2(ll);
                po.x = fmaf(sc, hf.x + lf.x, po.x);
                po.y = fmaf(sc, hf.y + lf.y, po.y);
            }
            // loop-top barrier protects A before next build
        }

        // ---- output (Red2 aliases dead H1 region) ----
        sm.h.Red2[tid] = po;
        __syncthreads();
        if (tid < 32) {
            float2 acc = sm.h.Red2[tid];
            #pragma unroll
            for (int g = 1; g < 8; g++) {
                float2 v = sm.h.Red2[g * 32 + tid];
                acc.x += v.x; acc.y += v.y;
            }
            out[b_cur * 64 + 2 * tid]     = acc.x;
            out[b_cur * 64 + 2 * tid + 1] = acc.y;
        }
        // counter self-reset: CTA finishing the globally-last batch restores g_ctr
        if (tid == 0) {
            int od = atomicAdd(&g_done, 1);
            if (od == BB - 1) {
                g_done = 0;
                __threadfence();
                g_ctr = GRID;
            }
        }
        b_cur = b_next;
    }
}

extern "C" void kernel_launch(void* const* d_in, const int* in_sizes, int n_in,
                              void* d_out, int out_size) {
    const float* q      = (const float*)d_in[0];
    const float* k      = (const float*)d_in[1];
    const int*   sl     = (const int*)  d_in[2];
    const float* W1     = (const float*)d_in[3];
    const float* alpha1 = (const float*)d_in[4];
    const float* mean1  = (const float*)d_in[5];
    const float* var1   = (const float*)d_in[6];
    const float* W2     = (const float*)d_in[7];
    const float* alpha2 = (const float*)d_in[8];
    const float* mean2  = (const float*)d_in[9];
    const float* var2   = (const float*)d_in[10];
    const float* W3     = (const float*)d_in[11];
    float* out = (float*)d_out;

    cudaFuncSetAttribute(din_pool_kernel,
                         cudaFuncAttributeMaxDynamicSharedMemorySize,
                         (int)sizeof(Smem));
    din_pool_kernel<<<GRID, 256, sizeof(Smem)>>>(
        q, k, sl, W1, alpha1, mean1, var1, W2, alpha2, mean2, var2, W3, out);
}

// round 17
// speedup vs baseline: 1.4616x; 1.1498x over previous
#include <cuda_runtime.h>
#include <cuda_bf16.h>
#include <cstdint>

#define BB 2048
#define SS 200
#define TS 64
#define EPSV 1e-9f
#define ASTRIDE 72    // bf16 row stride: 144B, granule stride 9 -> conflict-free ldmatrix
#define HSTRIDE 72
#define GRID 456      // 3 CTAs/SM x 152 SMs, persistent

__device__ int g_ctr  = GRID;   // work-pop counter; self-resets each launch
__device__ int g_done = 0;      // completed-batch counter; self-resets

struct alignas(16) Smem {
    __nv_bfloat16 Ahi[64][ASTRIDE];        // A = k tile, bf16 hi
    __nv_bfloat16 Alo[64][ASTRIDE];        // bf16 lo (residual)
    float Kraw[64][68];                    // cp.async staging of next K tile
    union {
        struct {
            __nv_bfloat16 H1hi[64][HSTRIDE];
            __nv_bfloat16 H1lo[64][HSTRIDE];
        } hh;                              // per-tile hidden
        float  Qpart[256];                 // batch-start qbias partials
        float2 Red2[256];                  // batch-end output reduce
    } h;
    uint32_t B2[32][33];                   // stage-2 W2 fragments, single shared copy
    float Spart[64];                       // stage-2 nt=1 partial scores
    float Score[64];
    float Q[64];
    float a1[64], m1[64], r1[64];
    float4 P2[16];                         // {mean2, rsqrt(var2+eps), alpha2, W3}
    int Lslot, bnext;
};

__device__ __forceinline__ float fast_sigmoid(float x) {
    return __fdividef(1.0f, 1.0f + __expf(-x));
}
__device__ __forceinline__ uint32_t sptr(const void* p) {
    return (uint32_t)__cvta_generic_to_shared(p);
}
__device__ __forceinline__ void ldsm4(uint32_t r[4], uint32_t addr) {
    asm volatile("ldmatrix.sync.aligned.m8n8.x4.shared.b16 {%0,%1,%2,%3}, [%4];"
                 : "=r"(r[0]), "=r"(r[1]), "=r"(r[2]), "=r"(r[3]) : "r"(addr));
}
__device__ __forceinline__ void mma16816(float c[4], const uint32_t a[4], const uint32_t b[2]) {
    asm volatile("mma.sync.aligned.m16n8k16.row.col.f32.bf16.bf16.f32 "
                 "{%0,%1,%2,%3},{%4,%5,%6,%7},{%8,%9},{%0,%1,%2,%3};"
                 : "+f"(c[0]), "+f"(c[1]), "+f"(c[2]), "+f"(c[3])
                 : "r"(a[0]), "r"(a[1]), "r"(a[2]), "r"(a[3]), "r"(b[0]), "r"(b[1]));
}
__device__ __forceinline__ void hl_split(float x, unsigned short& h, unsigned short& l) {
    __nv_bfloat16 hb = __float2bfloat16_rn(x);
    float r = x - __bfloat162float(hb);
    __nv_bfloat16 lb = __float2bfloat16_rn(r);
    h = __bfloat16_as_ushort(hb);
    l = __bfloat16_as_ushort(lb);
}
__device__ __forceinline__ uint32_t pk(unsigned short lo, unsigned short hi) {
    return ((uint32_t)hi << 16) | lo;
}
__device__ __forceinline__ void split2(float x, float y, uint32_t& ph, uint32_t& pl) {
    unsigned short xh, xl, yh, yl;
    hl_split(x, xh, xl);
    hl_split(y, yh, yl);
    ph = pk(xh, yh);
    pl = pk(xl, yl);
}
__device__ __forceinline__ float dice_apply(float x, float m, float r, float a) {
    float p = fast_sigmoid((x - m) * r);
    return x * (a + p * (1.0f - a));
}

__global__ void __launch_bounds__(256, 3) din_pool_kernel(
    const float* __restrict__ q_emb,
    const float* __restrict__ k_emb,
    const int*   __restrict__ seqlen,
    const float* __restrict__ W1,
    const float* __restrict__ alpha1,
    const float* __restrict__ mean1,
    const float* __restrict__ var1,
    const float* __restrict__ W2,
    const float* __restrict__ alpha2,
    const float* __restrict__ mean2,
    const float* __restrict__ var2,
    const float* __restrict__ W3,
    float* __restrict__ out)
{
    extern __shared__ char smem_raw[];
    Smem& sm = *reinterpret_cast<Smem*>(smem_raw);

    const int tid  = threadIdx.x;
    const int lane = tid & 31;
    const int wid  = tid >> 5;

    auto prefetch_tile = [&](int bb, int s0) {
        const long base = (long)bb * SS * 64;
        #pragma unroll
        for (int it = 0; it < 4; it++) {
            int i = tid + it * 256;
            int s = i >> 4, c4 = (i & 15) * 4;
            int gs = s0 + s;
            int gsc = (gs < SS) ? gs : 0;
            uint32_t dst = sptr(&sm.Kraw[s][c4]);
            const float* src = &k_emb[base + (long)gsc * 64 + c4];
            int szn = (gs < SS) ? 16 : 0;
            asm volatile("cp.async.ca.shared.global [%0], [%1], 16, %2;"
                         :: "r"(dst), "l"(src), "r"(szn));
        }
        asm volatile("cp.async.commit_group;");
    };

    // ---- issue tile-0 prefetch immediately; prologue hides it ----
    int b_cur = blockIdx.x;            // GRID < BB, always valid
    prefetch_tile(b_cur, 0);

    // ================= one-time prologue (no weight staging) =================
    if (tid < 16)
        sm.P2[tid] = make_float4(mean2[tid], rsqrtf(var2[tid] + EPSV),
                                 alpha2[tid], W3[tid]);
    if (tid < 64) {
        sm.a1[tid] = alpha1[tid];
        sm.m1[tid] = mean1[tid];
        sm.r1[tid] = rsqrtf(var1[tid] + EPSV);
    }
    // B2 fragments straight from gmem W2 (single shared copy; warp 0 builds)
    if (wid == 0) {
        int n = lane >> 2;
        #pragma unroll
        for (int kt = 0; kt < 4; kt++) {
            int kb = kt * 16 + 2 * (lane & 3);
            #pragma unroll
            for (int nt = 0; nt < 2; nt++) {
                int col = n + 8 * nt;
                float w0 = W2[kb * 16 + col];
                float w1 = W2[(kb + 1) * 16 + col];
                float w8 = W2[(kb + 8) * 16 + col];
                float w9 = W2[(kb + 9) * 16 + col];
                uint32_t h0, l0, h1, l1;
                split2(w0, w1, h0, l0);
                split2(w8, w9, h1, l1);
                sm.B2[lane][kt * 8 + nt * 4 + 0] = h0;
                sm.B2[lane][kt * 8 + nt * 4 + 1] = h1;
                sm.B2[lane][kt * 8 + nt * 4 + 2] = l0;
                sm.B2[lane][kt * 8 + nt * 4 + 3] = l1;
            }
        }
    }
    __syncthreads();

    // Hoisted constants
    const int n0   = 8 * wid + 2 * (lane & 3);    // stage-1 cols
    const float d1m0 = sm.m1[n0],     d1r0 = sm.r1[n0],     d1a0 = sm.a1[n0];
    const float d1m1 = sm.m1[n0 + 1], d1r1 = sm.r1[n0 + 1], d1a1 = sm.a1[n0 + 1];
    const int arow = lane & 15;
    const int acol = (lane & 16) ? 8 : 0;
    const int c4e   = (tid & 15) * 4;             // builder cols
    const int srow0 = tid >> 4;                   // builder base row
    const int eL   = tid & 31;
    const int er   = tid >> 5;
    // stage-2 mapping: warp w -> rows (w&3)*16, n-tile w>>2
    const int s2m  = wid & 3;
    const int s2nt = wid >> 2;

    // ================= persistent batch loop =================
    while (b_cur < BB) {
        if (tid == 0) {
            sm.bnext = atomicAdd(&g_ctr, 1);
            sm.Lslot = seqlen[b_cur];
        }
        if (tid < 64) sm.Q[tid] = q_emb[b_cur * 64 + tid];
        __syncthreads();
        const int L      = sm.Lslot;
        const int b_next = sm.bnext;
        const int T      = (L + TS - 1) >> 6;

        // ---- Qbias partials: q @ (W1a + W1c), coalesced gmem (L2/L1-hot) ----
        {
            int hcol = tid & 63, g = tid >> 6;
            const float* W1a = W1 + (g * 16) * 64 + hcol;
            const float* W1c = W1 + (128 + g * 16) * 64 + hcol;
            float acc = 0.f;
            #pragma unroll
            for (int d = 0; d < 16; d++)
                acc = fmaf(sm.Q[g * 16 + d], W1a[d * 64] + W1c[d * 64], acc);
            sm.h.Qpart[tid] = acc;
        }

        // ---- B1 fragments per batch: W_eff = (W1b - W1c) + q * W1d ----
        uint32_t b1hi[4][2], b1lo[4][2];
        {
            int n = 8 * wid + (lane >> 2);
            #pragma unroll
            for (int kt = 0; kt < 4; kt++) {
                int kb = kt * 16 + 2 * (lane & 3);
                float w[4];
                #pragma unroll
                for (int j = 0; j < 4; j++) {
                    int d = kb + ((j & 1) ? 1 : 0) + ((j & 2) ? 8 : 0);  // {0,1,8,9}
                    float wb = W1[(64 + d) * 64 + n];
                    float wc = W1[(128 + d) * 64 + n];
                    float wd = W1[(192 + d) * 64 + n];
                    w[j] = (wb - wc) + sm.Q[d] * wd;
                }
                split2(w[0], w[1], b1hi[kt][0], b1lo[kt][0]);
                split2(w[2], w[3], b1hi[kt][1], b1lo[kt][1]);
            }
        }
        __syncthreads();
        const float bia0 = sm.h.Qpart[n0]       + sm.h.Qpart[64 + n0]
                         + sm.h.Qpart[128 + n0] + sm.h.Qpart[192 + n0];
        const float bia1 = sm.h.Qpart[n0 + 1]       + sm.h.Qpart[64 + n0 + 1]
                         + sm.h.Qpart[128 + n0 + 1] + sm.h.Qpart[192 + n0 + 1];
        __syncthreads();   // Qpart reads done; h-region free for H1

        float2 po = make_float2(0.f, 0.f);

        for (int t = 0; t < T; t++) {
            const int s0 = t << 6;
            asm volatile("cp.async.wait_group 0;" ::: "memory");
            __syncthreads();   // Kraw ready; A free from prev epilogue

            // ---- build A (k only, bf16 hi/lo) from Kraw ----
            #pragma unroll
            for (int it = 0; it < 4; it++) {
                int s = srow0 + it * 16;
                float4 kv = *reinterpret_cast<const float4*>(&sm.Kraw[s][c4e]);
                uint32_t h0, l0, h1, l1;
                split2(kv.x, kv.y, h0, l0);
                split2(kv.z, kv.w, h1, l1);
                *reinterpret_cast<uint2*>(&sm.Ahi[s][c4e]) = make_uint2(h0, h1);
                *reinterpret_cast<uint2*>(&sm.Alo[s][c4e]) = make_uint2(l0, l1);
            }
            __syncthreads();   // A visible; Kraw free

            // ---- prefetch successor tile ----
            if (t + 1 < T)          prefetch_tile(b_cur, s0 + TS);
            else if (b_next < BB)   prefetch_tile(b_next, 0);

            // ---- stage 1: H1 = A(64x64) @ W_eff(64x64), 4 k-steps ----
            float c1[4][4];
            #pragma unroll
            for (int mi = 0; mi < 4; mi++) {
                c1[mi][0] = bia0; c1[mi][1] = bia1;
                c1[mi][2] = bia0; c1[mi][3] = bia1;
            }
            #pragma unroll
            for (int kt = 0; kt < 4; kt++) {
                #pragma unroll
                for (int mi = 0; mi < 4; mi++) {
                    uint32_t ah[4], al[4];
                    ldsm4(ah, sptr(&sm.Ahi[mi * 16 + arow][kt * 16 + acol]));
                    ldsm4(al, sptr(&sm.Alo[mi * 16 + arow][kt * 16 + acol]));
                    mma16816(c1[mi], ah, b1hi[kt]);
                    mma16816(c1[mi], al, b1hi[kt]);
                    mma16816(c1[mi], ah, b1lo[kt]);
                }
            }
            // Dice1 + store H1 hi/lo
            #pragma unroll
            for (int mi = 0; mi < 4; mi++) {
                int r0 = mi * 16 + (lane >> 2);
                uint32_t ph, pl;
                float x0 = dice_apply(c1[mi][0], d1m0, d1r0, d1a0);
                float x1 = dice_apply(c1[mi][1], d1m1, d1r1, d1a1);
                split2(x0, x1, ph, pl);
                *reinterpret_cast<uint32_t*>(&sm.h.hh.H1hi[r0][n0]) = ph;
                *reinterpret_cast<uint32_t*>(&sm.h.hh.H1lo[r0][n0]) = pl;
                float x2 = dice_apply(c1[mi][2], d1m0, d1r0, d1a0);
                float x3 = dice_apply(c1[mi][3], d1m1, d1r1, d1a1);
                split2(x2, x3, ph, pl);
                *reinterpret_cast<uint32_t*>(&sm.h.hh.H1hi[r0 + 8][n0]) = ph;
                *reinterpret_cast<uint32_t*>(&sm.h.hh.H1lo[r0 + 8][n0]) = pl;
            }
            __syncthreads();

            // ---- stage 2 on ALL 8 warps: warp = rows s2m*16, n-tile s2nt ----
            {
                const uint32_t* bp = &sm.B2[lane][0];
                float c2[4] = {0.f, 0.f, 0.f, 0.f};
                #pragma unroll
                for (int kt = 0; kt < 4; kt++) {
                    uint32_t ah[4], al[4];
                    ldsm4(ah, sptr(&sm.h.hh.H1hi[s2m * 16 + arow][kt * 16 + acol]));
                    ldsm4(al, sptr(&sm.h.hh.H1lo[s2m * 16 + arow][kt * 16 + acol]));
                    uint32_t bh[2] = { bp[kt * 8 + s2nt * 4 + 0], bp[kt * 8 + s2nt * 4 + 1] };
                    uint32_t bl[2] = { bp[kt * 8 + s2nt * 4 + 2], bp[kt * 8 + s2nt * 4 + 3] };
                    mma16816(c2, ah, bh);
                    mma16816(c2, al, bh);
                    mma16816(c2, ah, bl);
                }
                // dice2 + W3 partial over this warp's 8 cols
                int cc = 8 * s2nt + 2 * (lane & 3);
                float4 pA = sm.P2[cc];
                float4 pB = sm.P2[cc + 1];
                float pr0 = dice_apply(c2[0], pA.x, pA.y, pA.z) * pA.w
                          + dice_apply(c2[1], pB.x, pB.y, pB.z) * pB.w;
                float pr1 = dice_apply(c2[2], pA.x, pA.y, pA.z) * pA.w
                          + dice_apply(c2[3], pB.x, pB.y, pB.z) * pB.w;
                pr0 += __shfl_xor_sync(0xffffffffu, pr0, 1);
                pr0 += __shfl_xor_sync(0xffffffffu, pr0, 2);
                pr1 += __shfl_xor_sync(0xffffffffu, pr1, 1);
                pr1 += __shfl_xor_sync(0xffffffffu, pr1, 2);
                int r0 = s2m * 16 + (lane >> 2);
                if (s2nt == 1) {
                    if ((lane & 3) == 0) {
                        sm.Spart[r0]     = pr0;
                        sm.Spart[r0 + 8] = pr1;
                    }
                    asm volatile("bar.sync %0, 64;" :: "r"(1 + s2m) : "memory");
                } else {
                    asm volatile("bar.sync %0, 64;" :: "r"(1 + s2m) : "memory");
                    if ((lane & 3) == 0) {
                        int gs0 = s0 + r0;
                        float sA = pr0 + sm.Spart[r0];
                        float sB = pr1 + sm.Spart[r0 + 8];
                        sm.Score[r0]     = (gs0 < L)     ? fast_sigmoid(sA) : 0.0f;
                        sm.Score[r0 + 8] = (gs0 + 8 < L) ? fast_sigmoid(sB) : 0.0f;
                    }
                }
            }
            __syncthreads();

            // ---- epilogue: po += score[s] * k[s][cols], k = Ahi + Alo ----
            #pragma unroll
            for (int i = 0; i < 8; i++) {
                int s = (er << 3) + i;
                float sc = sm.Score[s];
                __nv_bfloat162 hh = *reinterpret_cast<const __nv_bfloat162*>(&sm.Ahi[s][2 * eL]);
                __nv_bfloat162 ll = *reinterpret_cast<const __nv_bfloat162*>(&sm.Alo[s][2 * eL]);
                float2 hf = __bfloat1622float2(hh);
                float2 lf = __bfloat1622float2(ll);
                po.x = fmaf(sc, hf.x + lf.x, po.x);
                po.y = fmaf(sc, hf.y + lf.y, po.y);
            }
            // loop-top barrier protects A before next build
        }

        // ---- output (Red2 aliases dead H1 region) ----
        sm.h.Red2[tid] = po;
        __syncthreads();
        if (tid < 32) {
            float2 acc = sm.h.Red2[tid];
            #pragma unroll
            for (int g = 1; g < 8; g++) {
                float2 v = sm.h.Red2[g * 32 + tid];
                acc.x += v.x; acc.y += v.y;
            }
            out[b_cur * 64 + 2 * tid]     = acc.x;
            out[b_cur * 64 + 2 * tid + 1] = acc.y;
        }
        // counter self-reset: CTA finishing the globally-last batch restores g_ctr
        if (tid == 0) {
            int od = atomicAdd(&g_done, 1);
            if (od == BB - 1) {
                g_done = 0;
                __threadfence();
                g_ctr = GRID;
            }
        }
        b_cur = b_next;
    }
}

extern "C" void kernel_launch(void* const* d_in, const int* in_sizes, int n_in,
                              void* d_out, int out_size) {
    const float* q      = (const float*)d_in[0];
    const float* k      = (const float*)d_in[1];
    const int*   sl     = (const int*)  d_in[2];
    const float* W1     = (const float*)d_in[3];
    const float* alpha1 = (const float*)d_in[4];
    const float* mean1  = (const float*)d_in[5];
    const float* var1   = (const float*)d_in[6];
    const float* W2     = (const float*)d_in[7];
    const float* alpha2 = (const float*)d_in[8];
    const float* mean2  = (const float*)d_in[9];
    const float* var2   = (const float*)d_in[10];
    const float* W3     = (const float*)d_in[11];
    float* out = (float*)d_out;

    cudaFuncSetAttribute(din_pool_kernel,
                         cudaFuncAttributeMaxDynamicSharedMemorySize,
                         (int)sizeof(Smem));
    din_pool_kernel<<<GRID, 256, sizeof(Smem)>>>(
        q, k, sl, W1, alpha1, mean1, var1, W2, alpha2, mean2, var2, W3, out);
}